// round 14
// baseline (speedup 1.0000x reference)
#include <cuda_runtime.h>
#include <cuda_fp16.h>
#include <cstdint>
#include <math.h>

#define IN_DIM  1024
#define OUT_DIM 1024
#define NE      8
#define NTOK    8192
#define KTOT    (NE * IN_DIM)
#define BM      128
#define BN      256

// SMEM layout (bytes)
#define SA_STAGE 8192                   // A: 16 m8 x 4 k8 x 128B blocks (raw fp16 x)
#define SB_STAGE 32768                  // B: 64 k-rows x 512B (swizzled 16B cols)
#define SB_BASE  (4 * SA_STAGE)                           // 32768
#define SG_BASE  (SB_BASE + 4 * SB_STAGE)                 // 163840
#define HG_BASE  (SG_BASE + 4096)                         // 167936
#define SMEM_BYTES (HG_BASE + 4096)                       // 172032

// ---------------- scratch ----------------
__device__ float    g_gates[NTOK * NE];              // softmax gates fp32
__device__ uint32_t g_hg[NTOK * NE];                 // h2(ge, ge) per (n, e)
__device__ __half   g_Wh[KTOT * OUT_DIM];            // fp16 We [K, O], 16 MB
__device__ __half   g_xh[NTOK * IN_DIM];             // fp16 x  [N, I], 16 MB

// ---------------- helpers ----------------
__device__ __forceinline__ uint32_t smem_u32(const void* p) {
    uint32_t a;
    asm("{ .reg .u64 t; cvta.to.shared.u64 t, %1; cvt.u32.u64 %0, t; }" : "=r"(a) : "l"(p));
    return a;
}
__device__ __forceinline__ uint32_t packh2(float lo, float hi) {
    uint32_t r;
    asm("cvt.rn.f16x2.f32 %0, %1, %2;" : "=r"(r) : "f"(hi), "f"(lo));
    return r;
}
__device__ __forceinline__ uint32_t mulh2(uint32_t a, uint32_t b) {
    uint32_t r;
    asm("mul.rn.f16x2 %0, %1, %2;" : "=r"(r) : "r"(a), "r"(b));
    return r;
}
// swizzled byte offset of 16B col-slot `col16` (0..31) in k-row `kr` (0..63) of a B stage
__device__ __forceinline__ uint32_t bswz(int kr, int col16) {
    return (uint32_t)(kr * 512 + ((((col16 ^ kr) & 7) | (col16 & 24)) << 4));
}

// ---------------- kernel 1: merged prep (gates + We fp16 + x fp16) ----------------
#define GATE_BLOCKS 256
__global__ __launch_bounds__(1024) void prep_kernel(const float* __restrict__ x,
                                                    const float* __restrict__ Wg,
                                                    const float* __restrict__ bg,
                                                    const float* __restrict__ We) {
    int tid = threadIdx.x;
    if (blockIdx.x < GATE_BLOCKS) {
        __shared__ float sW[NE * IN_DIM];
        for (int idx = tid; idx < NE * IN_DIM; idx += 1024) {
            int i = idx >> 3, e = idx & 7;
            sW[e * IN_DIM + i] = Wg[idx];
        }
        __syncthreads();
        int w = tid >> 5, lane = tid & 31;
        int n = blockIdx.x * 32 + w;
        float acc[NE];
#pragma unroll
        for (int e = 0; e < NE; e++) acc[e] = 0.f;
        const float* xr = x + (size_t)n * IN_DIM;
        for (int i = lane; i < IN_DIM; i += 32) {
            float xv = xr[i];
#pragma unroll
            for (int e = 0; e < NE; e++) acc[e] += xv * sW[e * IN_DIM + i];
        }
#pragma unroll
        for (int e = 0; e < NE; e++) {
#pragma unroll
            for (int off = 16; off; off >>= 1)
                acc[e] += __shfl_xor_sync(0xffffffffu, acc[e], off);
        }
        if (lane == 0) {
            float v[NE], m = -1e30f;
#pragma unroll
            for (int e = 0; e < NE; e++) { v[e] = acc[e] + bg[e]; m = fmaxf(m, v[e]); }
            float s = 0.f;
#pragma unroll
            for (int e = 0; e < NE; e++) { v[e] = expf(v[e] - m); s += v[e]; }
            float inv = 1.0f / s;
#pragma unroll
            for (int e = 0; e < NE; e++) {
                float ge = v[e] * inv;
                g_gates[n * NE + e] = ge;
                g_hg[n * NE + e] = packh2(ge, ge);
            }
        }
    } else {
        int totW = KTOT * OUT_DIM / 8;                 // 1M uint4 jobs (We)
        int totX = NTOK * IN_DIM / 8;                  // 1M uint4 jobs (x)
        int nthr = (gridDim.x - GATE_BLOCKS) * 1024;
        for (int idx = (blockIdx.x - GATE_BLOCKS) * 1024 + tid; idx < totW + totX; idx += nthr) {
            const float4* s;
            uint4* d;
            if (idx < totW) {
                s = (const float4*)We + (size_t)idx * 2;
                d = (uint4*)(g_Wh + (size_t)idx * 8);
            } else {
                int k = idx - totW;
                s = (const float4*)x + (size_t)k * 2;
                d = (uint4*)(g_xh + (size_t)k * 8);
            }
            float4 a = s[0], b = s[1];
            uint4 w;
            w.x = packh2(a.x, a.y); w.y = packh2(a.z, a.w);
            w.z = packh2(b.x, b.y); w.w = packh2(b.z, b.w);
            *d = w;
        }
    }
}

// ---------------- kernel 2: fused fp16 mma GEMM, register-gated A ----------------
// Chunk c (<128): ep = c>>5 (experts 2ep, 2ep+1), ic = c&31 (x cols ic*32..+32).
// A tile = RAW fp16 x [128 x 32]; gate applied in registers via mul.f16x2.
// A block (m8,k8 in 0..3) at (m8*4+k8)*128; row r8 at slot ((r8+4*k8)&7)*16.
__global__ __launch_bounds__(512, 1) void moe_mma_kernel(const float* __restrict__ be,
                                                         float* __restrict__ out) {
    extern __shared__ __align__(16) char smem[];
    const uint32_t aBase = smem_u32(smem);
    const uint32_t bBase = aBase + SB_BASE;
    float* sg = (float*)(smem + SG_BASE);
    uint32_t* hgT = (uint32_t*)(smem + HG_BASE);

    int tid = threadIdx.x;
    int m0 = blockIdx.y * BM, o0 = blockIdx.x * BN;

    for (int i = tid; i < BM * NE; i += 512) {
        sg[i] = g_gates[m0 * NE + i];
        hgT[i] = g_hg[m0 * NE + i];
    }
    __syncthreads();

    // ---- A producer: 4 threads per row, one 16B (8-half) slot each ----
    const int rowA = tid >> 2, ja = tid & 3;
    const int m8p = rowA >> 3, r8p = rowA & 7;
    const uint32_t aoff = (uint32_t)(((m8p * 4 + ja) * 128) + (((r8p + 4 * ja) & 7) * 16));
    const __half* xhrow = g_xh + (size_t)(m0 + rowA) * IN_DIM + ja * 8;

    // ---- B producer: 8 threads per k-row, 4 x 16B slots ----
    const int kr = tid >> 3, segB = tid & 7;
    uint32_t bd[4];
#pragma unroll
    for (int j = 0; j < 4; j++) bd[j] = bswz(kr, segB + 8 * j);

    auto produceA = [&](int st, int cc) {
        uint32_t dst = aBase + (uint32_t)st * SA_STAGE + aoff;
        if (cc < 128) {
            const __half* src = xhrow + (cc & 31) * 32;
            asm volatile("cp.async.cg.shared.global [%0], [%1], 16;" :: "r"(dst), "l"(src));
        } else {
            if (ja == 0) {
                const float* g = &sg[rowA * NE];
                asm volatile("st.shared.v4.b32 [%0], {%1,%2,%3,%4};" :: "r"(dst),
                             "r"(packh2(g[0], g[1])), "r"(packh2(g[2], g[3])),
                             "r"(packh2(g[4], g[5])), "r"(packh2(g[6], g[7])));
            } else {
                asm volatile("st.shared.v4.b32 [%0], {%1,%1,%1,%1};" :: "r"(dst), "r"(0u));
            }
        }
    };
    auto produceB = [&](int st, int cc) {
        uint32_t sbase = bBase + (uint32_t)st * SB_STAGE;
        if (cc < 128) {
            int ep = cc >> 5, ic = cc & 31;
            int expert = 2 * ep + (kr >> 5);
            const __half* src = g_Wh + (size_t)(expert * 1024 + ic * 32 + (kr & 31)) * OUT_DIM
                                + o0 + segB * 8;
#pragma unroll
            for (int j = 0; j < 4; j++)
                asm volatile("cp.async.cg.shared.global [%0], [%1], 16;"
                             :: "r"(sbase + bd[j]), "l"(src + 64 * j));
        } else {
            if (kr < 8) {
                const float* s0 = be + (size_t)kr * OUT_DIM + o0 + segB * 8;
#pragma unroll
                for (int j = 0; j < 4; j++) {
                    float4 a = *(const float4*)(s0 + 64 * j);
                    float4 b = *(const float4*)(s0 + 64 * j + 4);
                    asm volatile("st.shared.v4.b32 [%0], {%1,%2,%3,%4};" :: "r"(sbase + bd[j]),
                                 "r"(packh2(a.x, a.y)), "r"(packh2(a.z, a.w)),
                                 "r"(packh2(b.x, b.y)), "r"(packh2(b.z, b.w)));
                }
            } else {
#pragma unroll
                for (int j = 0; j < 4; j++)
                    asm volatile("st.shared.v4.b32 [%0], {%1,%1,%1,%1};" :: "r"(sbase + bd[j]), "r"(0u));
            }
        }
        asm volatile("cp.async.commit_group;");
    };

    // ---- accumulators / warp mapping (2m x 8n warps, 64x32 per warp) ----
    float acc[4][4][4];
#pragma unroll
    for (int mi = 0; mi < 4; mi++)
#pragma unroll
        for (int ni = 0; ni < 4; ni++)
#pragma unroll
            for (int q = 0; q < 4; q++) acc[mi][ni][q] = 0.f;

    int wid = tid >> 5, lane = tid & 31;
    int wm = (wid & 1) * 64, wn = (wid >> 1) * 32;
    int lr = lane >> 2, lc = lane & 3;
    const int wmBlk = (wid & 1) * 8;
    const int wn8 = (wid >> 1) * 4;

    // A ldmatrix lane constant (A block row stride = 4 k8 = 512B)
    const int jm = (lane >> 3) & 1, jk = lane >> 4, rr = lane & 7;
    const uint32_t aLane = (uint32_t)(jm * 512 + jk * 128 + (((rr + 4 * jk) & 7) * 16));
    // B ldmatrix.trans lane constants
    const int jb = lane >> 3, rb = lane & 7;
    const int kb = 8 * (jb & 1) + rb;
    const int nb = jb >> 1;

    uint32_t hg[2][4][2];    // [expert][mi][row-half] gate h2

#define MMA(ACC, T0, T1, T2, T3, B0, B1)                                              \
    asm volatile("mma.sync.aligned.m16n8k16.row.col.f32.f16.f16.f32 "                 \
                 "{%0,%1,%2,%3}, {%4,%5,%6,%7}, {%8,%9}, {%0,%1,%2,%3};"              \
                 : "+f"((ACC)[0]), "+f"((ACC)[1]), "+f"((ACC)[2]), "+f"((ACC)[3])     \
                 : "r"(T0), "r"(T1), "r"(T2), "r"(T3), "r"(B0), "r"(B1))

    auto compute = [&](int st) {
        const uint32_t A = aBase + (uint32_t)st * SA_STAGE + aLane;
        const uint32_t B = bBase + (uint32_t)st * SB_STAGE;
#pragma unroll
        for (int g = 0; g < 2; g++) {
            uint32_t bf0[4][2], bf1[4][2];
#pragma unroll
            for (int p = 0; p < 2; p++) {
                uint32_t addr = B + bswz(g * 16 + kb, wn8 + 2 * p + nb);
                asm volatile("ldmatrix.sync.aligned.m8n8.x4.trans.shared.b16 {%0,%1,%2,%3}, [%4];"
                             : "=r"(bf0[2 * p][0]), "=r"(bf0[2 * p][1]),
                               "=r"(bf0[2 * p + 1][0]), "=r"(bf0[2 * p + 1][1]) : "r"(addr));
            }
#pragma unroll
            for (int p = 0; p < 2; p++) {
                uint32_t addr = B + bswz(32 + g * 16 + kb, wn8 + 2 * p + nb);
                asm volatile("ldmatrix.sync.aligned.m8n8.x4.trans.shared.b16 {%0,%1,%2,%3}, [%4];"
                             : "=r"(bf1[2 * p][0]), "=r"(bf1[2 * p][1]),
                               "=r"(bf1[2 * p + 1][0]), "=r"(bf1[2 * p + 1][1]) : "r"(addr));
            }
#pragma unroll
            for (int mi = 0; mi < 4; mi++) {
                uint32_t x0, x1, x2, x3;
                uint32_t addr = A + (uint32_t)((wmBlk + 2 * mi) * 512 + g * 256);
                asm volatile("ldmatrix.sync.aligned.m8n8.x4.shared.b16 {%0,%1,%2,%3}, [%4];"
                             : "=r"(x0), "=r"(x1), "=r"(x2), "=r"(x3) : "r"(addr));
                uint32_t t0 = mulh2(x0, hg[0][mi][0]), t1 = mulh2(x1, hg[0][mi][1]);
                uint32_t t2 = mulh2(x2, hg[0][mi][0]), t3 = mulh2(x3, hg[0][mi][1]);
#pragma unroll
                for (int ni = 0; ni < 4; ni++)
                    MMA(acc[mi][ni], t0, t1, t2, t3, bf0[ni][0], bf0[ni][1]);
                t0 = mulh2(x0, hg[1][mi][0]); t1 = mulh2(x1, hg[1][mi][1]);
                t2 = mulh2(x2, hg[1][mi][0]); t3 = mulh2(x3, hg[1][mi][1]);
#pragma unroll
                for (int ni = 0; ni < 4; ni++)
                    MMA(acc[mi][ni], t0, t1, t2, t3, bf1[ni][0], bf1[ni][1]);
            }
        }
    };

    // ---- prologue: produce chunks 0, 1 into stages 0, 1 ----
    produceA(0, 0); produceB(0, 0);
    produceA(1, 1); produceB(1, 1);

    // ---- paired main loop: one barrier per 2 chunks ----
#pragma unroll 1
    for (int c = 0; c < 128; c += 2) {
        asm volatile("cp.async.wait_group 0;" ::: "memory");
        __syncthreads();
        produceA((c + 2) & 3, c + 2);
        produceB((c + 2) & 3, c + 2);
        if (c + 3 <= 128) {
            produceA((c + 3) & 3, c + 3);
            produceB((c + 3) & 3, c + 3);
        }
        if ((c & 31) == 0) {
            int ep = c >> 5;
#pragma unroll
            for (int mi = 0; mi < 4; mi++)
#pragma unroll
                for (int rs = 0; rs < 2; rs++) {
                    int rowg = wm + mi * 16 + lr + rs * 8;
                    hg[0][mi][rs] = hgT[rowg * NE + 2 * ep];
                    hg[1][mi][rs] = hgT[rowg * NE + 2 * ep + 1];
                }
        }
        compute(c & 3);
        compute((c + 1) & 3);
    }

    // ---- tail: bias chunk 128 (stage 0), raw fragments, g=0 only ----
    asm volatile("cp.async.wait_group 0;" ::: "memory");
    __syncthreads();
    {
        const uint32_t A = aBase + aLane;
        const uint32_t B = bBase;
        uint32_t bfb[4][2];
#pragma unroll
        for (int p = 0; p < 2; p++) {
            uint32_t addr = B + bswz(kb, wn8 + 2 * p + nb);
            asm volatile("ldmatrix.sync.aligned.m8n8.x4.trans.shared.b16 {%0,%1,%2,%3}, [%4];"
                         : "=r"(bfb[2 * p][0]), "=r"(bfb[2 * p][1]),
                           "=r"(bfb[2 * p + 1][0]), "=r"(bfb[2 * p + 1][1]) : "r"(addr));
        }
#pragma unroll
        for (int mi = 0; mi < 4; mi++) {
            uint32_t x0, x1, x2, x3;
            uint32_t addr = A + (uint32_t)((wmBlk + 2 * mi) * 512);
            asm volatile("ldmatrix.sync.aligned.m8n8.x4.shared.b16 {%0,%1,%2,%3}, [%4];"
                         : "=r"(x0), "=r"(x1), "=r"(x2), "=r"(x3) : "r"(addr));
#pragma unroll
            for (int ni = 0; ni < 4; ni++)
                MMA(acc[mi][ni], x0, x1, x2, x3, bfb[ni][0], bfb[ni][1]);
        }
    }

    // ---- epilogue: pure store ----
#pragma unroll
    for (int mi = 0; mi < 4; mi++) {
        int r = m0 + wm + mi * 16 + lr;
#pragma unroll
        for (int ni = 0; ni < 4; ni++) {
            int cc = o0 + wn + ni * 8 + lc * 2;
            *(float2*)(out + (size_t)r * OUT_DIM + cc) =
                make_float2(acc[mi][ni][0], acc[mi][ni][1]);
            *(float2*)(out + (size_t)(r + 8) * OUT_DIM + cc) =
                make_float2(acc[mi][ni][2], acc[mi][ni][3]);
        }
    }
#undef MMA
}

// ---------------- launch ----------------
extern "C" void kernel_launch(void* const* d_in, const int* in_sizes, int n_in,
                              void* d_out, int out_size) {
    const float* x  = (const float*)d_in[0];
    const float* We = (const float*)d_in[1];
    const float* be = (const float*)d_in[2];
    const float* Wg = (const float*)d_in[3];
    const float* bg = (const float*)d_in[4];
    float* out = (float*)d_out;

    cudaFuncSetAttribute(moe_mma_kernel, cudaFuncAttributeMaxDynamicSharedMemorySize, SMEM_BYTES);

    prep_kernel<<<GATE_BLOCKS + 768, 1024>>>(x, Wg, bg, We);
    moe_mma_kernel<<<dim3(OUT_DIM / BN, NTOK / BM), 512, SMEM_BYTES>>>(be, out);
}

// round 15
// speedup vs baseline: 1.1646x; 1.1646x over previous
#include <cuda_runtime.h>
#include <cuda_fp16.h>
#include <cstdint>
#include <math.h>

#define IN_DIM  1024
#define OUT_DIM 1024
#define NE      8
#define NTOK    8192
#define KTOT    (NE * IN_DIM)
#define BM      128
#define BN      256
#define STAGES  4

// SMEM per stage (bytes)
#define SA_STAGE 16384                  // A: 16 m8 x 8 k8 x 128B blocks
#define SB_STAGE 32768                  // B: 64 k-rows x 512B (swizzled 16B cols)
#define SB_BASE  (STAGES * SA_STAGE)                      // 65536
#define SG_BASE  (SB_BASE + STAGES * SB_STAGE)            // 196608
#define SMEM_BYTES (SG_BASE + BM * NE * 4)                // 200704

// ---------------- scratch ----------------
__device__ float  g_gates[NTOK * NE];                // softmax gates [N, E]
__device__ __half g_Wh[KTOT * OUT_DIM];              // fp16 We, [K, O] row-major, 16 MB

// ---------------- helpers ----------------
__device__ __forceinline__ uint32_t smem_u32(const void* p) {
    uint32_t a;
    asm("{ .reg .u64 t; cvta.to.shared.u64 t, %1; cvt.u32.u64 %0, t; }" : "=r"(a) : "l"(p));
    return a;
}
__device__ __forceinline__ uint32_t packh2(float lo, float hi) {
    uint32_t r;
    asm("cvt.rn.f16x2.f32 %0, %1, %2;" : "=r"(r) : "f"(hi), "f"(lo));
    return r;
}
// swizzled byte offset of 16B col-slot `col16` (0..31) in k-row `kr` (0..63) of a B stage
__device__ __forceinline__ uint32_t bswz(int kr, int col16) {
    return (uint32_t)(kr * 512 + ((((col16 ^ kr) & 7) | (col16 & 24)) << 4));
}

// ---------------- kernel 1: merged prep (gate softmax + weight convert) ----------------
#define GATE_BLOCKS 256
__global__ __launch_bounds__(1024) void prep_kernel(const float* __restrict__ x,
                                                    const float* __restrict__ Wg,
                                                    const float* __restrict__ bg,
                                                    const float* __restrict__ We) {
    int tid = threadIdx.x;
    if (blockIdx.x < GATE_BLOCKS) {
        __shared__ float sW[NE * IN_DIM];
        for (int idx = tid; idx < NE * IN_DIM; idx += 1024) {
            int i = idx >> 3, e = idx & 7;
            sW[e * IN_DIM + i] = Wg[idx];
        }
        __syncthreads();
        int w = tid >> 5, lane = tid & 31;
        int n = blockIdx.x * 32 + w;
        float acc[NE];
#pragma unroll
        for (int e = 0; e < NE; e++) acc[e] = 0.f;
        const float* xr = x + (size_t)n * IN_DIM;
        for (int i = lane; i < IN_DIM; i += 32) {
            float xv = xr[i];
#pragma unroll
            for (int e = 0; e < NE; e++) acc[e] += xv * sW[e * IN_DIM + i];
        }
#pragma unroll
        for (int e = 0; e < NE; e++) {
#pragma unroll
            for (int off = 16; off; off >>= 1)
                acc[e] += __shfl_xor_sync(0xffffffffu, acc[e], off);
        }
        if (lane == 0) {
            float v[NE], m = -1e30f;
#pragma unroll
            for (int e = 0; e < NE; e++) { v[e] = acc[e] + bg[e]; m = fmaxf(m, v[e]); }
            float s = 0.f;
#pragma unroll
            for (int e = 0; e < NE; e++) { v[e] = expf(v[e] - m); s += v[e]; }
            float inv = 1.0f / s;
#pragma unroll
            for (int e = 0; e < NE; e++) g_gates[n * NE + e] = v[e] * inv;
        }
    } else {
        int total = KTOT * OUT_DIM / 8;
        int nthr = (gridDim.x - GATE_BLOCKS) * 1024;
        for (int idx = (blockIdx.x - GATE_BLOCKS) * 1024 + tid; idx < total; idx += nthr) {
            const float4* s = (const float4*)We + (size_t)idx * 2;
            float4 a = s[0], b = s[1];
            uint4 w;
            w.x = packh2(a.x, a.y); w.y = packh2(a.z, a.w);
            w.z = packh2(b.x, b.y); w.w = packh2(b.z, b.w);
            *(uint4*)(g_Wh + (size_t)idx * 8) = w;
        }
    }
}

// ---------------- kernel 2: fused fp16 mma GEMM, K=64 chunks, staggered ks phases ----------------
__global__ __launch_bounds__(512, 1) void moe_mma_kernel(const float* __restrict__ x,
                                                         const float* __restrict__ be,
                                                         float* __restrict__ out) {
    extern __shared__ __align__(16) char smem[];
    const uint32_t aBase = smem_u32(smem);
    const uint32_t bBase = aBase + SB_BASE;
    float* sg = (float*)(smem + SG_BASE);

    int tid = threadIdx.x;
    int m0 = blockIdx.y * BM, o0 = blockIdx.x * BN;

    for (int i = tid; i < BM * NE; i += 512) sg[i] = g_gates[m0 * NE + i];
    __syncthreads();

    // ---- A producer mapping: 4 threads per row, quads k8=qa and k8=qa+4 ----
    const int row = tid >> 2, qa = tid & 3;
    const int m8p = row >> 3, r8p = row & 7;
    const uint32_t sw_row = (uint32_t)(((r8p + 4 * qa) & 7) * 16);
    const uint32_t aoffQ0 = (uint32_t)((m8p * 8 + qa) * 128) + sw_row;
    const uint32_t aoffQ1 = (uint32_t)((m8p * 8 + qa + 4) * 128) + sw_row;
    const float* xrow = x + (size_t)(m0 + row) * IN_DIM;

    float4 xc0 = *(const float4*)(xrow + qa * 8);
    float4 xc1 = *(const float4*)(xrow + qa * 8 + 4);
    float4 xn0 = xc0, xn1 = xc1;

    // ---- B producer mapping: 8 threads per k-row, 4 x 16B slots ----
    const int kr = tid >> 3, segB = tid & 7;
    uint32_t bd[4];
#pragma unroll
    for (int j = 0; j < 4; j++) bd[j] = bswz(kr, segB + 8 * j);

    auto produceB = [&](int st, int cc) {
        uint32_t sbase = bBase + (uint32_t)st * SB_STAGE;
        if (cc < 128) {
            int ic = cc >> 2, t = cc & 3;
            int expert = 2 * t + (kr >> 5);
            const __half* src = g_Wh + (size_t)(expert * 1024 + ic * 32 + (kr & 31)) * OUT_DIM
                                + o0 + segB * 8;
#pragma unroll
            for (int j = 0; j < 4; j++)
                asm volatile("cp.async.cg.shared.global [%0], [%1], 16;"
                             :: "r"(sbase + bd[j]), "l"(src + 64 * j));
        } else {
            if (kr < 8) {
                const float* s0 = be + (size_t)kr * OUT_DIM + o0 + segB * 8;
#pragma unroll
                for (int j = 0; j < 4; j++) {
                    float4 a = *(const float4*)(s0 + 64 * j);
                    float4 b = *(const float4*)(s0 + 64 * j + 4);
                    asm volatile("st.shared.v4.b32 [%0], {%1,%2,%3,%4};" :: "r"(sbase + bd[j]),
                                 "r"(packh2(a.x, a.y)), "r"(packh2(a.z, a.w)),
                                 "r"(packh2(b.x, b.y)), "r"(packh2(b.z, b.w)));
                }
            } else {
#pragma unroll
                for (int j = 0; j < 4; j++)
                    asm volatile("st.shared.v4.b32 [%0], {%1,%1,%1,%1};" :: "r"(sbase + bd[j]), "r"(0u));
            }
        }
        asm volatile("cp.async.commit_group;");
    };
    auto produceA = [&](int st, int cc) {
        uint32_t base = aBase + (uint32_t)st * SA_STAGE;
        if (cc < 128) {
            int t = cc & 3, ic = cc >> 2;
            if (t == 0 && cc > 0) { xc0 = xn0; xc1 = xn1; }
            float ge0 = sg[row * NE + 2 * t];
            float ge1 = sg[row * NE + 2 * t + 1];
            asm volatile("st.shared.v4.b32 [%0], {%1,%2,%3,%4};" :: "r"(base + aoffQ0),
                         "r"(packh2(xc0.x * ge0, xc0.y * ge0)), "r"(packh2(xc0.z * ge0, xc0.w * ge0)),
                         "r"(packh2(xc1.x * ge0, xc1.y * ge0)), "r"(packh2(xc1.z * ge0, xc1.w * ge0)));
            asm volatile("st.shared.v4.b32 [%0], {%1,%2,%3,%4};" :: "r"(base + aoffQ1),
                         "r"(packh2(xc0.x * ge1, xc0.y * ge1)), "r"(packh2(xc0.z * ge1, xc0.w * ge1)),
                         "r"(packh2(xc1.x * ge1, xc1.y * ge1)), "r"(packh2(xc1.z * ge1, xc1.w * ge1)));
            if (t == 1 && ic < 31) {
                const float* p = xrow + (ic + 1) * 32 + qa * 8;
                xn0 = *(const float4*)p;
                xn1 = *(const float4*)(p + 4);
            }
        } else {
            if (qa == 0) {
                const float* g = &sg[row * NE];
                asm volatile("st.shared.v4.b32 [%0], {%1,%2,%3,%4};" :: "r"(base + aoffQ0),
                             "r"(packh2(g[0], g[1])), "r"(packh2(g[2], g[3])),
                             "r"(packh2(g[4], g[5])), "r"(packh2(g[6], g[7])));
            } else {
                asm volatile("st.shared.v4.b32 [%0], {%1,%1,%1,%1};" :: "r"(base + aoffQ0), "r"(0u));
            }
            asm volatile("st.shared.v4.b32 [%0], {%1,%1,%1,%1};" :: "r"(base + aoffQ1), "r"(0u));
        }
    };

    // ---- accumulators / warp mapping (2m x 8n warps, 64x32 per warp) ----
    float acc[4][4][4];
#pragma unroll
    for (int mi = 0; mi < 4; mi++)
#pragma unroll
        for (int ni = 0; ni < 4; ni++)
#pragma unroll
            for (int q = 0; q < 4; q++) acc[mi][ni][q] = 0.f;

    int wid = tid >> 5, lane = tid & 31;
    int wm = (wid & 1) * 64, wn = (wid >> 1) * 32;
    int lr = lane >> 2, lc = lane & 3;
    const int wmBlk = (wid & 1) * 8;
    const int wn8 = (wid >> 1) * 4;
    const int ksRot = wid & 3;                    // stagger k-group phases across warps

    const int jm = (lane >> 3) & 1, jk = lane >> 4, rr = lane & 7;
    const uint32_t aLane = (uint32_t)(jm * 1024 + jk * 128 + (((rr + 4 * jk) & 7) * 16));
    const int jb = lane >> 3, rb = lane & 7;
    const int kb = 8 * (jb & 1) + rb;
    const int nb = jb >> 1;

    auto compute = [&](int st) {
        const uint32_t A = aBase + (uint32_t)st * SA_STAGE + aLane;
        const uint32_t B = bBase + (uint32_t)st * SB_STAGE;
#pragma unroll
        for (int kss = 0; kss < 4; kss++) {
            int ks = (kss + ksRot) & 3;
            uint32_t bf[4][2];
#pragma unroll
            for (int p = 0; p < 2; p++) {
                int krL = 16 * ks + kb;
                int col16 = wn8 + 2 * p + nb;
                uint32_t addr = B + bswz(krL, col16);
                asm volatile("ldmatrix.sync.aligned.m8n8.x4.trans.shared.b16 {%0,%1,%2,%3}, [%4];"
                             : "=r"(bf[2 * p][0]), "=r"(bf[2 * p][1]),
                               "=r"(bf[2 * p + 1][0]), "=r"(bf[2 * p + 1][1])
                             : "r"(addr));
            }
#pragma unroll
            for (int mi = 0; mi < 4; mi++) {
                uint32_t a0, a1, a2, a3;
                uint32_t addr = A + (uint32_t)((wmBlk + 2 * mi) * 1024 + ks * 256);
                asm volatile("ldmatrix.sync.aligned.m8n8.x4.shared.b16 {%0,%1,%2,%3}, [%4];"
                             : "=r"(a0), "=r"(a1), "=r"(a2), "=r"(a3) : "r"(addr));
#pragma unroll
                for (int ni = 0; ni < 4; ni++)
                    asm volatile(
                        "mma.sync.aligned.m16n8k16.row.col.f32.f16.f16.f32 "
                        "{%0,%1,%2,%3}, {%4,%5,%6,%7}, {%8,%9}, {%0,%1,%2,%3};"
                        : "+f"(acc[mi][ni][0]), "+f"(acc[mi][ni][1]),
                          "+f"(acc[mi][ni][2]), "+f"(acc[mi][ni][3])
                        : "r"(a0), "r"(a1), "r"(a2), "r"(a3),
                          "r"(bf[ni][0]), "r"(bf[ni][1]));
            }
        }
    };

    // ---- prologue: produce chunks 0, 1 into stages 0, 1 ----
    produceA(0, 0); produceB(0, 0);
    produceA(1, 1); produceB(1, 1);

    // ---- paired main loop: one barrier per 2 chunks, produce interleaved ----
#pragma unroll 1
    for (int c = 0; c < 128; c += 2) {
        asm volatile("cp.async.wait_group 0;" ::: "memory");
        __syncthreads();
        produceA((c + 2) & 3, c + 2);
        produceB((c + 2) & 3, c + 2);
        compute(c & 3);
        if (c + 3 <= 128) {
            produceA((c + 3) & 3, c + 3);
            produceB((c + 3) & 3, c + 3);
        }
        compute((c + 1) & 3);
    }
    // ---- tail: bias chunk 128 (stage 0) ----
    asm volatile("cp.async.wait_group 0;" ::: "memory");
    __syncthreads();
    compute(0);

    // ---- epilogue: pure store (bias folded into GEMM) ----
#pragma unroll
    for (int mi = 0; mi < 4; mi++) {
        int r = m0 + wm + mi * 16 + lr;
#pragma unroll
        for (int ni = 0; ni < 4; ni++) {
            int cc = o0 + wn + ni * 8 + lc * 2;
            *(float2*)(out + (size_t)r * OUT_DIM + cc) =
                make_float2(acc[mi][ni][0], acc[mi][ni][1]);
            *(float2*)(out + (size_t)(r + 8) * OUT_DIM + cc) =
                make_float2(acc[mi][ni][2], acc[mi][ni][3]);
        }
    }
}

// ---------------- launch ----------------
extern "C" void kernel_launch(void* const* d_in, const int* in_sizes, int n_in,
                              void* d_out, int out_size) {
    const float* x  = (const float*)d_in[0];
    const float* We = (const float*)d_in[1];
    const float* be = (const float*)d_in[2];
    const float* Wg = (const float*)d_in[3];
    const float* bg = (const float*)d_in[4];
    float* out = (float*)d_out;

    cudaFuncSetAttribute(moe_mma_kernel, cudaFuncAttributeMaxDynamicSharedMemorySize, SMEM_BYTES);

    prep_kernel<<<GATE_BLOCKS + 768, 1024>>>(x, Wg, bg, We);
    moe_mma_kernel<<<dim3(OUT_DIM / BN, NTOK / BM), 512, SMEM_BYTES>>>(x, be, out);
}

// round 16
// speedup vs baseline: 1.2598x; 1.0817x over previous
#include <cuda_runtime.h>
#include <cuda_fp16.h>
#include <cstdint>
#include <math.h>

#define IN_DIM  1024
#define OUT_DIM 1024
#define NE      8
#define NTOK    8192
#define KTOT    (NE * IN_DIM)
#define BM      128
#define BN      256
#define STAGES  4

// SMEM per stage (bytes)
#define SA_STAGE 16384                  // A: 16 m8 x 8 k8 x 128B blocks
#define SB_STAGE 32768                  // B: 64 k-rows x 512B (swizzled 16B cols)
#define SB_BASE  (STAGES * SA_STAGE)                      // 65536
#define SG_BASE  (SB_BASE + STAGES * SB_STAGE)            // 196608
#define SMEM_BYTES (SG_BASE + BM * NE * 4)                // 200704

// ---------------- scratch ----------------
__device__ float  g_gates[NTOK * NE];                // softmax gates [N, E]
__device__ __half g_Wh[KTOT * OUT_DIM];              // fp16 We, [K, O] row-major, 16 MB

// ---------------- helpers ----------------
__device__ __forceinline__ uint32_t smem_u32(const void* p) {
    uint32_t a;
    asm("{ .reg .u64 t; cvta.to.shared.u64 t, %1; cvt.u32.u64 %0, t; }" : "=r"(a) : "l"(p));
    return a;
}
__device__ __forceinline__ uint32_t packh2(float lo, float hi) {
    uint32_t r;
    asm("cvt.rn.f16x2.f32 %0, %1, %2;" : "=r"(r) : "f"(hi), "f"(lo));
    return r;
}
// swizzled byte offset of 16B col-slot `col16` (0..31) in k-row `kr` (0..63) of a B stage
__device__ __forceinline__ uint32_t bswz(int kr, int col16) {
    return (uint32_t)(kr * 512 + ((((col16 ^ kr) & 7) | (col16 & 24)) << 4));
}

// ---------------- kernel 1: merged prep (gate softmax + weight convert) ----------------
#define GATE_BLOCKS 256
__global__ __launch_bounds__(1024) void prep_kernel(const float* __restrict__ x,
                                                    const float* __restrict__ Wg,
                                                    const float* __restrict__ bg,
                                                    const float* __restrict__ We) {
    int tid = threadIdx.x;
    if (blockIdx.x < GATE_BLOCKS) {
        __shared__ float sW[NE * IN_DIM];
        for (int idx = tid; idx < NE * IN_DIM; idx += 1024) {
            int i = idx >> 3, e = idx & 7;
            sW[e * IN_DIM + i] = Wg[idx];
        }
        __syncthreads();
        int w = tid >> 5, lane = tid & 31;
        int n = blockIdx.x * 32 + w;
        float acc[NE];
#pragma unroll
        for (int e = 0; e < NE; e++) acc[e] = 0.f;
        const float* xr = x + (size_t)n * IN_DIM;
        for (int i = lane; i < IN_DIM; i += 32) {
            float xv = xr[i];
#pragma unroll
            for (int e = 0; e < NE; e++) acc[e] += xv * sW[e * IN_DIM + i];
        }
#pragma unroll
        for (int e = 0; e < NE; e++) {
#pragma unroll
            for (int off = 16; off; off >>= 1)
                acc[e] += __shfl_xor_sync(0xffffffffu, acc[e], off);
        }
        if (lane == 0) {
            float v[NE], m = -1e30f;
#pragma unroll
            for (int e = 0; e < NE; e++) { v[e] = acc[e] + bg[e]; m = fmaxf(m, v[e]); }
            float s = 0.f;
#pragma unroll
            for (int e = 0; e < NE; e++) { v[e] = expf(v[e] - m); s += v[e]; }
            float inv = 1.0f / s;
#pragma unroll
            for (int e = 0; e < NE; e++) g_gates[n * NE + e] = v[e] * inv;
        }
    } else {
        int total = KTOT * OUT_DIM / 8;
        int nthr = (gridDim.x - GATE_BLOCKS) * 1024;
        for (int idx = (blockIdx.x - GATE_BLOCKS) * 1024 + tid; idx < total; idx += nthr) {
            const float4* s = (const float4*)We + (size_t)idx * 2;
            float4 a = s[0], b = s[1];
            uint4 w;
            w.x = packh2(a.x, a.y); w.y = packh2(a.z, a.w);
            w.z = packh2(b.x, b.y); w.w = packh2(b.z, b.w);
            *(uint4*)(g_Wh + (size_t)idx * 8) = w;
        }
    }
}

// ---------------- kernel 2: fused fp16 mma GEMM, register-pipelined fragments ----------------
__global__ __launch_bounds__(512, 1) void moe_mma_kernel(const float* __restrict__ x,
                                                         const float* __restrict__ be,
                                                         float* __restrict__ out) {
    extern __shared__ __align__(16) char smem[];
    const uint32_t aBase = smem_u32(smem);
    const uint32_t bBase = aBase + SB_BASE;
    float* sg = (float*)(smem + SG_BASE);

    int tid = threadIdx.x;
    int m0 = blockIdx.y * BM, o0 = blockIdx.x * BN;

    for (int i = tid; i < BM * NE; i += 512) sg[i] = g_gates[m0 * NE + i];
    __syncthreads();

    // ---- A producer mapping: 4 threads per row, quads k8=qa and k8=qa+4 ----
    const int row = tid >> 2, qa = tid & 3;
    const int m8p = row >> 3, r8p = row & 7;
    const uint32_t sw_row = (uint32_t)(((r8p + 4 * qa) & 7) * 16);
    const uint32_t aoffQ0 = (uint32_t)((m8p * 8 + qa) * 128) + sw_row;
    const uint32_t aoffQ1 = (uint32_t)((m8p * 8 + qa + 4) * 128) + sw_row;
    const float* xrow = x + (size_t)(m0 + row) * IN_DIM;

    float4 xc0 = *(const float4*)(xrow + qa * 8);
    float4 xc1 = *(const float4*)(xrow + qa * 8 + 4);
    float4 xn0 = xc0, xn1 = xc1;

    // ---- B producer mapping: 8 threads per k-row, 4 x 16B slots ----
    const int kr = tid >> 3, segB = tid & 7;
    uint32_t bd[4];
#pragma unroll
    for (int j = 0; j < 4; j++) bd[j] = bswz(kr, segB + 8 * j);

    auto produceB = [&](int st, int cc) {
        uint32_t sbase = bBase + (uint32_t)st * SB_STAGE;
        if (cc < 128) {
            int ic = cc >> 2, t = cc & 3;
            int expert = 2 * t + (kr >> 5);
            const __half* src = g_Wh + (size_t)(expert * 1024 + ic * 32 + (kr & 31)) * OUT_DIM
                                + o0 + segB * 8;
#pragma unroll
            for (int j = 0; j < 4; j++)
                asm volatile("cp.async.cg.shared.global [%0], [%1], 16;"
                             :: "r"(sbase + bd[j]), "l"(src + 64 * j));
        } else {
            if (kr < 8) {
                const float* s0 = be + (size_t)kr * OUT_DIM + o0 + segB * 8;
#pragma unroll
                for (int j = 0; j < 4; j++) {
                    float4 a = *(const float4*)(s0 + 64 * j);
                    float4 b = *(const float4*)(s0 + 64 * j + 4);
                    asm volatile("st.shared.v4.b32 [%0], {%1,%2,%3,%4};" :: "r"(sbase + bd[j]),
                                 "r"(packh2(a.x, a.y)), "r"(packh2(a.z, a.w)),
                                 "r"(packh2(b.x, b.y)), "r"(packh2(b.z, b.w)));
                }
            } else {
#pragma unroll
                for (int j = 0; j < 4; j++)
                    asm volatile("st.shared.v4.b32 [%0], {%1,%1,%1,%1};" :: "r"(sbase + bd[j]), "r"(0u));
            }
        }
        asm volatile("cp.async.commit_group;");
    };
    auto produceA = [&](int st, int cc) {
        uint32_t base = aBase + (uint32_t)st * SA_STAGE;
        if (cc < 128) {
            int t = cc & 3, ic = cc >> 2;
            if (t == 0 && cc > 0) { xc0 = xn0; xc1 = xn1; }
            float ge0 = sg[row * NE + 2 * t];
            float ge1 = sg[row * NE + 2 * t + 1];
            asm volatile("st.shared.v4.b32 [%0], {%1,%2,%3,%4};" :: "r"(base + aoffQ0),
                         "r"(packh2(xc0.x * ge0, xc0.y * ge0)), "r"(packh2(xc0.z * ge0, xc0.w * ge0)),
                         "r"(packh2(xc1.x * ge0, xc1.y * ge0)), "r"(packh2(xc1.z * ge0, xc1.w * ge0)));
            asm volatile("st.shared.v4.b32 [%0], {%1,%2,%3,%4};" :: "r"(base + aoffQ1),
                         "r"(packh2(xc0.x * ge1, xc0.y * ge1)), "r"(packh2(xc0.z * ge1, xc0.w * ge1)),
                         "r"(packh2(xc1.x * ge1, xc1.y * ge1)), "r"(packh2(xc1.z * ge1, xc1.w * ge1)));
            if (t == 1 && ic < 31) {
                const float* p = xrow + (ic + 1) * 32 + qa * 8;
                xn0 = *(const float4*)p;
                xn1 = *(const float4*)(p + 4);
            }
        } else {
            if (qa == 0) {
                const float* g = &sg[row * NE];
                asm volatile("st.shared.v4.b32 [%0], {%1,%2,%3,%4};" :: "r"(base + aoffQ0),
                             "r"(packh2(g[0], g[1])), "r"(packh2(g[2], g[3])),
                             "r"(packh2(g[4], g[5])), "r"(packh2(g[6], g[7])));
            } else {
                asm volatile("st.shared.v4.b32 [%0], {%1,%1,%1,%1};" :: "r"(base + aoffQ0), "r"(0u));
            }
            asm volatile("st.shared.v4.b32 [%0], {%1,%1,%1,%1};" :: "r"(base + aoffQ1), "r"(0u));
        }
    };

    // ---- accumulators / warp mapping (2m x 8n warps, 64x32 per warp) ----
    float acc[4][4][4];
#pragma unroll
    for (int mi = 0; mi < 4; mi++)
#pragma unroll
        for (int ni = 0; ni < 4; ni++)
#pragma unroll
            for (int q = 0; q < 4; q++) acc[mi][ni][q] = 0.f;

    int wid = tid >> 5, lane = tid & 31;
    int wm = (wid & 1) * 64, wn = (wid >> 1) * 32;
    int lr = lane >> 2, lc = lane & 3;
    const int wmBlk = (wid & 1) * 8;
    const int wn8 = (wid >> 1) * 4;

    const int jm = (lane >> 3) & 1, jk = lane >> 4, rr = lane & 7;
    const uint32_t aLane = (uint32_t)(jm * 1024 + jk * 128 + (((rr + 4 * jk) & 7) * 16));
    const int jb = lane >> 3, rb = lane & 7;
    const int kb = 8 * (jb & 1) + rb;
    const int nb = jb >> 1;

#define LDM_A(dst, Abase, mi_, ks_)                                                   \
    asm volatile("ldmatrix.sync.aligned.m8n8.x4.shared.b16 {%0,%1,%2,%3}, [%4];"      \
                 : "=r"((dst)[0]), "=r"((dst)[1]), "=r"((dst)[2]), "=r"((dst)[3])     \
                 : "r"((Abase) + (uint32_t)((wmBlk + 2 * (mi_)) * 1024 + (ks_) * 256)))
#define LDM_B(dst, Bbase, ks_, p_)                                                    \
    asm volatile("ldmatrix.sync.aligned.m8n8.x4.trans.shared.b16 {%0,%1,%2,%3}, [%4];" \
                 : "=r"((dst)[2 * (p_)][0]), "=r"((dst)[2 * (p_)][1]),                \
                   "=r"((dst)[2 * (p_) + 1][0]), "=r"((dst)[2 * (p_) + 1][1])         \
                 : "r"((Bbase) + bswz(16 * (ks_) + kb, wn8 + 2 * (p_) + nb)))
#define MMA(ACC, AF, B0, B1)                                                          \
    asm volatile("mma.sync.aligned.m16n8k16.row.col.f32.f16.f16.f32 "                 \
                 "{%0,%1,%2,%3}, {%4,%5,%6,%7}, {%8,%9}, {%0,%1,%2,%3};"              \
                 : "+f"((ACC)[0]), "+f"((ACC)[1]), "+f"((ACC)[2]), "+f"((ACC)[3])     \
                 : "r"((AF)[0]), "r"((AF)[1]), "r"((AF)[2]), "r"((AF)[3]),            \
                   "r"(B0), "r"(B1))

    auto compute = [&](int st) {
        const uint32_t A = aBase + (uint32_t)st * SA_STAGE + aLane;
        const uint32_t B = bBase + (uint32_t)st * SB_STAGE;
        uint32_t bf[2][4][2];     // [buf][ni][half] double-buffered B fragments
        uint32_t af[2][4];        // double-buffered A fragment (one mi)
        LDM_B(bf[0], B, 0, 0);
        LDM_B(bf[0], B, 0, 1);
        LDM_A(af[0], A, 0, 0);
#pragma unroll
        for (int ks = 0; ks < 4; ks++) {
#pragma unroll
            for (int mi = 0; mi < 4; mi++) {
                const int buf = (ks * 4 + mi) & 1;
                // prefetch next A fragment
                if (mi < 3) {
                    LDM_A(af[buf ^ 1], A, mi + 1, ks);
                } else if (ks < 3) {
                    LDM_A(af[buf ^ 1], A, 0, ks + 1);
                }
                // prefetch next B fragments mid-stream
                if (mi == 1 && ks < 3) LDM_B(bf[(ks + 1) & 1], B, ks + 1, 0);
                if (mi == 2 && ks < 3) LDM_B(bf[(ks + 1) & 1], B, ks + 1, 1);
#pragma unroll
                for (int ni = 0; ni < 4; ni++)
                    MMA(acc[mi][ni], af[buf], bf[ks & 1][ni][0], bf[ks & 1][ni][1]);
            }
        }
    };

    // ---- prologue: produce chunks 0, 1 into stages 0, 1 ----
    produceA(0, 0); produceB(0, 0);
    produceA(1, 1); produceB(1, 1);

    // ---- paired main loop: one barrier per 2 chunks, produce interleaved ----
#pragma unroll 1
    for (int c = 0; c < 128; c += 2) {
        asm volatile("cp.async.wait_group 0;" ::: "memory");
        __syncthreads();
        produceA((c + 2) & 3, c + 2);
        produceB((c + 2) & 3, c + 2);
        compute(c & 3);
        if (c + 3 <= 128) {
            produceA((c + 3) & 3, c + 3);
            produceB((c + 3) & 3, c + 3);
        }
        compute((c + 1) & 3);
    }
    // ---- tail: bias chunk 128 (stage 0) ----
    asm volatile("cp.async.wait_group 0;" ::: "memory");
    __syncthreads();
    compute(0);

    // ---- epilogue: pure store (bias folded into GEMM) ----
#pragma unroll
    for (int mi = 0; mi < 4; mi++) {
        int r = m0 + wm + mi * 16 + lr;
#pragma unroll
        for (int ni = 0; ni < 4; ni++) {
            int cc = o0 + wn + ni * 8 + lc * 2;
            *(float2*)(out + (size_t)r * OUT_DIM + cc) =
                make_float2(acc[mi][ni][0], acc[mi][ni][1]);
            *(float2*)(out + (size_t)(r + 8) * OUT_DIM + cc) =
                make_float2(acc[mi][ni][2], acc[mi][ni][3]);
        }
    }
#undef LDM_A
#undef LDM_B
#undef MMA
}

// ---------------- launch ----------------
extern "C" void kernel_launch(void* const* d_in, const int* in_sizes, int n_in,
                              void* d_out, int out_size) {
    const float* x  = (const float*)d_in[0];
    const float* We = (const float*)d_in[1];
    const float* be = (const float*)d_in[2];
    const float* Wg = (const float*)d_in[3];
    const float* bg = (const float*)d_in[4];
    float* out = (float*)d_out;

    cudaFuncSetAttribute(moe_mma_kernel, cudaFuncAttributeMaxDynamicSharedMemorySize, SMEM_BYTES);

    prep_kernel<<<GATE_BLOCKS + 768, 1024>>>(x, Wg, bg, We);
    moe_mma_kernel<<<dim3(OUT_DIM / BN, NTOK / BM), 512, SMEM_BYTES>>>(x, be, out);
}